// round 1
// baseline (speedup 1.0000x reference)
#include <cuda_runtime.h>

// Net_60413009985719 — the reference "5-layer LSTM over L=500000" collapses:
//   * h_prev is zeroed inside _lstm_step  -> no recurrence, Whh*/f-gate dead
//   * head reads only h[-1:]              -> only x[L-1] matters
// So the whole net is: scalar -> 5x (256x64 affine + lstm-gate nonlinearity)
// -> 32-wide ReLU fc -> {mean, log_std, relu(16)->value}. One block, 256 thr.

#define H 64
#define G 256  // 4*H

__device__ __forceinline__ float sigf(float x) {
    return 1.0f / (1.0f + expf(-x));
}

__global__ void net_kernel(const float* __restrict__ x, long long L,
                           const float* __restrict__ Wih0,   // (256,1)
                           const float* __restrict__ bih0,   // (256)
                           const float* __restrict__ bhh0,   // (256)
                           const float* __restrict__ Wih,    // (4,256,64)
                           const float* __restrict__ bih,    // (4,256)
                           const float* __restrict__ bhh,    // (4,256)
                           const float* __restrict__ fc_w,   // (32,64)
                           const float* __restrict__ fc_b,   // (32)
                           const float* __restrict__ mean_w, // (1,32)
                           const float* __restrict__ mean_b, // (1)
                           const float* __restrict__ ls_w,   // (1,32)
                           const float* __restrict__ ls_b,   // (1)
                           const float* __restrict__ c1_w,   // (16,32)
                           const float* __restrict__ c1_b,   // (16)
                           const float* __restrict__ c2_w,   // (1,16)
                           const float* __restrict__ c2_b,   // (1)
                           float* __restrict__ out)          // [mean, log_std, v]
{
    __shared__ float sh_h[H];
    __shared__ float sh_g[G];
    __shared__ float sh_z[32];
    __shared__ float sh_vh[16];
    __shared__ float sh_scal[2];  // mean, log_std

    const int t = threadIdx.x;  // 0..255
    const float xv = x[L - 1];

    // ---- layer 0: gates from scalar input ----
    sh_g[t] = xv * Wih0[t] + bih0[t] + bhh0[t];
    __syncthreads();
    if (t < H) {
        float iv = sigf(sh_g[t]);
        float gv = tanhf(sh_g[2 * H + t]);
        float ov = sigf(sh_g[3 * H + t]);
        sh_h[t] = ov * tanhf(iv * gv);
    }
    __syncthreads();

    // ---- layers 1..4: 256x64 matvec + gate nonlinearity ----
    for (int l = 0; l < 4; ++l) {
        const float* W = Wih + ((long)l * G + t) * H;
        float acc = bih[l * G + t] + bhh[l * G + t];
        #pragma unroll
        for (int k = 0; k < H; ++k)
            acc += sh_h[k] * W[k];
        sh_g[t] = acc;
        __syncthreads();
        if (t < H) {
            float iv = sigf(sh_g[t]);
            float gv = tanhf(sh_g[2 * H + t]);
            float ov = sigf(sh_g[3 * H + t]);
            sh_h[t] = ov * tanhf(iv * gv);
        }
        __syncthreads();
    }

    // ---- head: z = relu(h @ fc_w.T + fc_b) ----
    if (t < 32) {
        const float* W = fc_w + t * H;
        float acc = fc_b[t];
        #pragma unroll
        for (int k = 0; k < H; ++k)
            acc += sh_h[k] * W[k];
        sh_z[t] = fmaxf(acc, 0.0f);
    }
    __syncthreads();

    // vh = relu(z @ c1_w.T + c1_b); mean; log_std — all in parallel
    if (t < 16) {
        const float* W = c1_w + t * 32;
        float acc = c1_b[t];
        #pragma unroll
        for (int k = 0; k < 32; ++k)
            acc += sh_z[k] * W[k];
        sh_vh[t] = fmaxf(acc, 0.0f);
    } else if (t == 16) {
        float acc = mean_b[0];
        #pragma unroll
        for (int k = 0; k < 32; ++k)
            acc += sh_z[k] * mean_w[k];
        sh_scal[0] = acc;
    } else if (t == 17) {
        float acc = ls_b[0];
        #pragma unroll
        for (int k = 0; k < 32; ++k)
            acc += sh_z[k] * ls_w[k];
        sh_scal[1] = acc;
    }
    __syncthreads();

    if (t == 0) {
        float acc = c2_b[0];
        #pragma unroll
        for (int k = 0; k < 16; ++k)
            acc += sh_vh[k] * c2_w[k];
        out[0] = sh_scal[0];
        out[1] = sh_scal[1];
        out[2] = acc;
    }
}

extern "C" void kernel_launch(void* const* d_in, const int* in_sizes, int n_in,
                              void* d_out, int out_size) {
    // metadata order:
    // 0:x 1:Wih0 2:Whh0 3:bih0 4:bhh0 5:Wih 6:Whh 7:bih 8:bhh
    // 9:fc_w 10:fc_b 11:mean_w 12:mean_b 13:ls_w 14:ls_b
    // 15:c1_w 16:c1_b 17:c2_w 18:c2_b
    const float* x      = (const float*)d_in[0];
    const float* Wih0   = (const float*)d_in[1];
    const float* bih0   = (const float*)d_in[3];
    const float* bhh0   = (const float*)d_in[4];
    const float* Wih    = (const float*)d_in[5];
    const float* bih    = (const float*)d_in[7];
    const float* bhh    = (const float*)d_in[8];
    const float* fc_w   = (const float*)d_in[9];
    const float* fc_b   = (const float*)d_in[10];
    const float* mean_w = (const float*)d_in[11];
    const float* mean_b = (const float*)d_in[12];
    const float* ls_w   = (const float*)d_in[13];
    const float* ls_b   = (const float*)d_in[14];
    const float* c1_w   = (const float*)d_in[15];
    const float* c1_b   = (const float*)d_in[16];
    const float* c2_w   = (const float*)d_in[17];
    const float* c2_b   = (const float*)d_in[18];

    long long L = in_sizes[0];

    net_kernel<<<1, 256>>>(x, L, Wih0, bih0, bhh0, Wih, bih, bhh,
                           fc_w, fc_b, mean_w, mean_b, ls_w, ls_b,
                           c1_w, c1_b, c2_w, c2_b, (float*)d_out);
}

// round 2
// speedup vs baseline: 3.5948x; 3.5948x over previous
#include <cuda_runtime.h>
#include <cstdint>

// Net_60413009985719 — collapsed net (no recurrence, only x[L-1] matters,
// LSTM f-gate dead). Strategy: stream ALL live weights (~200KB) into SMEM
// via cp.async up front (per-layer commit groups), then run the whole
// 5-layer chain + head out of SMEM. One block, 512 threads.

#define H 64
#define ROWS 192          // live gate rows per layer (i, g, o; f is dead)
#define NT 512

// ---- shared layout (float offsets) ----
#define OFF_W    0                      // [4][192][64]
#define OFF_FC   (OFF_W + 4*ROWS*H)     // [32][64]
#define OFF_W0   (OFF_FC + 32*H)        // [192]
#define OFF_B0   (OFF_W0 + ROWS)        // [192]
#define OFF_BS   (OFF_B0 + ROWS)        // [4][192]
#define OFF_C1W  (OFF_BS + 4*ROWS)      // [16][32]
#define OFF_C1B  (OFF_C1W + 512)        // [16]
#define OFF_FCB  (OFF_C1B + 16)         // [32]
#define OFF_MW   (OFF_FCB + 32)         // [32]
#define OFF_LSW  (OFF_MW + 32)          // [32]
#define OFF_C2W  (OFF_LSW + 32)         // [16]
#define OFF_SC   (OFF_C2W + 16)         // [3] mean_b, ls_b, c2_b
#define OFF_H    (OFF_SC + 3)           // [64]
#define OFF_G    (OFF_H + H)            // [192]
#define OFF_Z    (OFF_G + ROWS)         // [32]
#define OFF_VH   (OFF_Z + 32)           // [16]
#define OFF_SCAL (OFF_VH + 16)          // [2]
#define SMEM_FLOATS (OFF_SCAL + 2)
#define SMEM_BYTES  (SMEM_FLOATS * 4)

__device__ __forceinline__ float sigf(float v) { return 1.0f / (1.0f + expf(-v)); }

__device__ __forceinline__ void cp16(uint32_t dst_smem, const void* src) {
    asm volatile("cp.async.cg.shared.global [%0], [%1], 16;" :: "r"(dst_smem), "l"(src));
}
__device__ __forceinline__ void cp_commit() {
    asm volatile("cp.async.commit_group;");
}
template <int N>
__device__ __forceinline__ void cp_wait() {
    asm volatile("cp.async.wait_group %0;" :: "n"(N));
}

__global__ void __launch_bounds__(NT, 1)
net_kernel(const float* __restrict__ x, long long L,
           const float* __restrict__ Wih0,   // (256,1)
           const float* __restrict__ bih0,   // (256)
           const float* __restrict__ bhh0,   // (256)
           const float* __restrict__ Wih,    // (4,256,64)
           const float* __restrict__ bih,    // (4,256)
           const float* __restrict__ bhh,    // (4,256)
           const float* __restrict__ fc_w,   // (32,64)
           const float* __restrict__ fc_b,   // (32)
           const float* __restrict__ mean_w, // (32)
           const float* __restrict__ mean_b, // (1)
           const float* __restrict__ ls_w,   // (32)
           const float* __restrict__ ls_b,   // (1)
           const float* __restrict__ c1_w,   // (16,32)
           const float* __restrict__ c1_b,   // (16)
           const float* __restrict__ c2_w,   // (16)
           const float* __restrict__ c2_b,   // (1)
           float* __restrict__ out)
{
    extern __shared__ float sm[];
    const int tid = threadIdx.x;
    const uint32_t smbase = (uint32_t)__cvta_generic_to_shared(sm);

    // ---- 1) stream big weights, one commit group per layer, then fc ----
    // shared row r (0..191) <-> gmem gate row: i:[0,64) g:[128,192) o:[192,256)
    #pragma unroll
    for (int l = 0; l < 4; ++l) {
        for (int c = tid; c < ROWS * 16; c += NT) {       // 16B chunks
            int r = c >> 4, ch = c & 15;
            int grow = (r < 64) ? r : r + 64;
            uint32_t dst = smbase + (uint32_t)((OFF_W + (l * ROWS + r) * H + ch * 4) * 4);
            cp16(dst, Wih + ((size_t)l * 256 + grow) * H + ch * 4);
        }
        cp_commit();
    }
    for (int c = tid; c < 32 * 16; c += NT) {
        int r = c >> 4, ch = c & 15;
        cp16(smbase + (uint32_t)((OFF_FC + r * H + ch * 4) * 4), fc_w + r * H + ch * 4);
    }
    cp_commit();

    // ---- 2) stage small tensors (plain LDG->STS, overlapped with cp.async) ----
    const float xv = x[L - 1];
    for (int j = tid; j < ROWS; j += NT) {
        int grow = (j < 64) ? j : j + 64;
        sm[OFF_W0 + j] = Wih0[grow];
        sm[OFF_B0 + j] = bih0[grow] + bhh0[grow];
    }
    for (int j = tid; j < 4 * ROWS; j += NT) {
        int l = j / ROWS, r = j - l * ROWS;
        int grow = (r < 64) ? r : r + 64;
        sm[OFF_BS + j] = bih[l * 256 + grow] + bhh[l * 256 + grow];
    }
    for (int j = tid; j < 512; j += NT) sm[OFF_C1W + j] = c1_w[j];
    if (tid < 32) {
        sm[OFF_FCB + tid] = fc_b[tid];
        sm[OFF_MW + tid]  = mean_w[tid];
        sm[OFF_LSW + tid] = ls_w[tid];
    }
    if (tid < 16) {
        sm[OFF_C1B + tid] = c1_b[tid];
        sm[OFF_C2W + tid] = c2_w[tid];
    }
    if (tid == 0) {
        sm[OFF_SC + 0] = mean_b[0];
        sm[OFF_SC + 1] = ls_b[0];
        sm[OFF_SC + 2] = c2_b[0];
    }
    __syncthreads();

    // ---- 3) layer 0: gates from scalar ----
    if (tid < ROWS) sm[OFF_G + tid] = xv * sm[OFF_W0 + tid] + sm[OFF_B0 + tid];
    __syncthreads();
    if (tid < H) {
        float iv = sigf(sm[OFF_G + tid]);
        float gv = tanhf(sm[OFF_G + 64 + tid]);
        float ov = sigf(sm[OFF_G + 128 + tid]);
        sm[OFF_H + tid] = ov * tanhf(iv * gv);
    }
    // (sync is at top of layer loop, combined with cp.async wait)

    // ---- 4) layers 1..4 from SMEM; wait only for the needed commit group ----
    #pragma unroll
    for (int l = 0; l < 4; ++l) {
        switch (l) {           // wait until groups 0..l have landed
            case 0: cp_wait<4>(); break;
            case 1: cp_wait<3>(); break;
            case 2: cp_wait<2>(); break;
            case 3: cp_wait<1>(); break;
        }
        __syncthreads();       // copies visible to all + prev H ready
        if (tid < ROWS) {
            const float* Wr = sm + OFF_W + (l * ROWS + tid) * H;
            float acc = sm[OFF_BS + l * ROWS + tid];
            #pragma unroll
            for (int k = 0; k < H; ++k) {
                int kk = (k + tid) & (H - 1);   // rotation: conflict-free SMEM
                acc += sm[OFF_H + kk] * Wr[kk];
            }
            sm[OFF_G + tid] = acc;
        }
        __syncthreads();
        if (tid < H) {
            float iv = sigf(sm[OFF_G + tid]);
            float gv = tanhf(sm[OFF_G + 64 + tid]);
            float ov = sigf(sm[OFF_G + 128 + tid]);
            sm[OFF_H + tid] = ov * tanhf(iv * gv);
        }
    }

    cp_wait<0>();              // fc weights
    __syncthreads();

    // ---- 5) head ----
    if (tid < 32) {
        const float* Wr = sm + OFF_FC + tid * H;
        float acc = sm[OFF_FCB + tid];
        #pragma unroll
        for (int k = 0; k < H; ++k) {
            int kk = (k + tid) & (H - 1);
            acc += sm[OFF_H + kk] * Wr[kk];
        }
        sm[OFF_Z + tid] = fmaxf(acc, 0.0f);
    }
    __syncthreads();

    if (tid < 16) {
        const float* Wr = sm + OFF_C1W + tid * 32;
        float acc = sm[OFF_C1B + tid];
        #pragma unroll
        for (int k = 0; k < 32; ++k) {
            int kk = (k + 2 * tid) & 31;        // conflict-free
            acc += sm[OFF_Z + kk] * Wr[kk];
        }
        sm[OFF_VH + tid] = fmaxf(acc, 0.0f);
    } else if (tid == 16) {
        float acc = sm[OFF_SC + 0];
        #pragma unroll
        for (int k = 0; k < 32; ++k) acc += sm[OFF_Z + k] * sm[OFF_MW + k];
        sm[OFF_SCAL + 0] = acc;
    } else if (tid == 17) {
        float acc = sm[OFF_SC + 1];
        #pragma unroll
        for (int k = 0; k < 32; ++k) acc += sm[OFF_Z + k] * sm[OFF_LSW + k];
        sm[OFF_SCAL + 1] = acc;
    }
    __syncthreads();

    if (tid == 0) {
        float acc = sm[OFF_SC + 2];
        #pragma unroll
        for (int k = 0; k < 16; ++k) acc += sm[OFF_VH + k] * sm[OFF_C2W + k];
        out[0] = sm[OFF_SCAL + 0];
        out[1] = sm[OFF_SCAL + 1];
        out[2] = acc;
    }
}

extern "C" void kernel_launch(void* const* d_in, const int* in_sizes, int n_in,
                              void* d_out, int out_size) {
    const float* x      = (const float*)d_in[0];
    const float* Wih0   = (const float*)d_in[1];
    const float* bih0   = (const float*)d_in[3];
    const float* bhh0   = (const float*)d_in[4];
    const float* Wih    = (const float*)d_in[5];
    const float* bih    = (const float*)d_in[7];
    const float* bhh    = (const float*)d_in[8];
    const float* fc_w   = (const float*)d_in[9];
    const float* fc_b   = (const float*)d_in[10];
    const float* mean_w = (const float*)d_in[11];
    const float* mean_b = (const float*)d_in[12];
    const float* ls_w   = (const float*)d_in[13];
    const float* ls_b   = (const float*)d_in[14];
    const float* c1_w   = (const float*)d_in[15];
    const float* c1_b   = (const float*)d_in[16];
    const float* c2_w   = (const float*)d_in[17];
    const float* c2_b   = (const float*)d_in[18];

    long long L = in_sizes[0];

    static bool attr_set = false;
    if (!attr_set) {
        cudaFuncSetAttribute(net_kernel,
                             cudaFuncAttributeMaxDynamicSharedMemorySize, SMEM_BYTES);
        attr_set = true;
    }

    net_kernel<<<1, NT, SMEM_BYTES>>>(x, L, Wih0, bih0, bhh0, Wih, bih, bhh,
                                      fc_w, fc_b, mean_w, mean_b, ls_w, ls_b,
                                      c1_w, c1_b, c2_w, c2_b, (float*)d_out);
}

// round 4
// speedup vs baseline: 4.1190x; 1.1458x over previous
#include <cuda_runtime.h>
#include <cstdint>

// Net_60413009985719 — collapsed net (no recurrence, only x[L-1] matters,
// LSTM f-gate dead). R4 = R3 (TMA bulk loads + LDS.128 matvec) with the
// float4 alignment bug fixed: OFF_H is now 16B-aligned (R3 trapped on a
// misaligned LDS.128 at sm+OFF_H). One block, 512 threads.

#define H 64
#define ROWS 192          // live gate rows per layer (i, g, o; f is dead)
#define NT 512

// ---- shared layout (float offsets; float4-read regions 16B-aligned) ----
#define OFF_W    0                      // [4][192][64]   (rows 64-float aligned)
#define OFF_FC   (OFF_W + 4*ROWS*H)     // [32][64]       (rows 64-float aligned)
#define OFF_W0   (OFF_FC + 32*H)        // [192]
#define OFF_B0   (OFF_W0 + ROWS)        // [192]
#define OFF_BS   (OFF_B0 + ROWS)        // [4][192]
#define OFF_C1W  (OFF_BS + 4*ROWS)      // [16][32]
#define OFF_C1B  (OFF_C1W + 512)        // [16]
#define OFF_FCB  (OFF_C1B + 16)         // [32]
#define OFF_MW   (OFF_FCB + 32)         // [32]
#define OFF_LSW  (OFF_MW + 32)          // [32]
#define OFF_C2W  (OFF_LSW + 32)         // [16]
#define OFF_SC   (OFF_C2W + 16)         // [3] mean_b, ls_b, c2_b
#define OFF_H    (((OFF_SC + 3) + 3) & ~3)  // [64], 16B-aligned (float4 reads)
#define OFF_G    (OFF_H + H)            // [192]
#define OFF_Z    (OFF_G + ROWS)         // [32]
#define OFF_VH   (OFF_Z + 32)           // [16]
#define OFF_SCAL (OFF_VH + 16)          // [2]
#define OFF_MBAR (((OFF_SCAL + 2) + 1) & ~1)   // 8B-aligned; 5 x u64 = 10 floats
#define SMEM_FLOATS (OFF_MBAR + 10)
#define SMEM_BYTES  (SMEM_FLOATS * 4)

// compile-time alignment audit for every float4-accessed base
static_assert((OFF_H % 4) == 0, "h vector must be 16B-aligned");
static_assert((OFF_W % 4) == 0 && (H % 4) == 0, "W rows must be 16B-aligned");
static_assert((OFF_FC % 4) == 0, "fc rows must be 16B-aligned");
static_assert((OFF_MBAR % 2) == 0, "mbarrier must be 8B-aligned");

__device__ __forceinline__ float sigf(float v) { return 1.0f / (1.0f + expf(-v)); }

__device__ __forceinline__ void mbar_init(uint32_t addr, uint32_t count) {
    asm volatile("mbarrier.init.shared.b64 [%0], %1;" :: "r"(addr), "r"(count) : "memory");
}
__device__ __forceinline__ void mbar_expect(uint32_t addr, uint32_t bytes) {
    asm volatile("mbarrier.arrive.expect_tx.shared.b64 _, [%0], %1;"
                 :: "r"(addr), "r"(bytes) : "memory");
}
__device__ __forceinline__ void bulk_g2s(uint32_t dst, const void* src,
                                         uint32_t bytes, uint32_t mbar) {
    asm volatile("cp.async.bulk.shared::cta.global.mbarrier::complete_tx::bytes "
                 "[%0], [%1], %2, [%3];"
                 :: "r"(dst), "l"(src), "r"(bytes), "r"(mbar) : "memory");
}
__device__ __forceinline__ void mbar_wait0(uint32_t addr) {
    asm volatile(
        "{\n\t"
        ".reg .pred P;\n\t"
        "WAIT_%=:\n\t"
        "mbarrier.try_wait.parity.acquire.cta.shared::cta.b64 P, [%0], 0, 0x989680;\n\t"
        "@P bra.uni DONE_%=;\n\t"
        "bra.uni WAIT_%=;\n\t"
        "DONE_%=:\n\t"
        "}" :: "r"(addr) : "memory");
}
__device__ __forceinline__ void fence_proxy_async_sc() {
    asm volatile("fence.proxy.async.shared::cta;" ::: "memory");
}

__global__ void __launch_bounds__(NT, 1)
net_kernel(const float* __restrict__ x, long long L,
           const float* __restrict__ Wih0,   // (256,1)
           const float* __restrict__ bih0,   // (256)
           const float* __restrict__ bhh0,   // (256)
           const float* __restrict__ Wih,    // (4,256,64)
           const float* __restrict__ bih,    // (4,256)
           const float* __restrict__ bhh,    // (4,256)
           const float* __restrict__ fc_w,   // (32,64)
           const float* __restrict__ fc_b,   // (32)
           const float* __restrict__ mean_w, // (32)
           const float* __restrict__ mean_b, // (1)
           const float* __restrict__ ls_w,   // (32)
           const float* __restrict__ ls_b,   // (1)
           const float* __restrict__ c1_w,   // (16,32)
           const float* __restrict__ c1_b,   // (16)
           const float* __restrict__ c2_w,   // (16)
           const float* __restrict__ c2_b,   // (1)
           float* __restrict__ out)
{
    extern __shared__ __align__(16) float sm[];
    const int tid = threadIdx.x;
    const uint32_t smbase = (uint32_t)__cvta_generic_to_shared(sm);
    const uint32_t mbar = smbase + OFF_MBAR * 4;

    // ---- 1) TMA bulk copies for all big weights (issued by thread 0) ----
    if (tid == 0) {
        #pragma unroll
        for (int i = 0; i < 5; ++i) mbar_init(mbar + 8 * i, 1);
        fence_proxy_async_sc();
        #pragma unroll
        for (int l = 0; l < 4; ++l) {
            uint32_t mb = mbar + 8 * l;
            mbar_expect(mb, ROWS * H * 4);                 // 49152 B
            // i-gate rows 0..63 (16 KB, contiguous in gmem)
            bulk_g2s(smbase + (OFF_W + (l * ROWS) * H) * 4,
                     Wih + (size_t)l * 256 * H, 64 * H * 4, mb);
            // g+o rows 128..255 (32 KB, contiguous in gmem)
            bulk_g2s(smbase + (OFF_W + (l * ROWS + 64) * H) * 4,
                     Wih + ((size_t)l * 256 + 128) * H, 128 * H * 4, mb);
        }
        mbar_expect(mbar + 8 * 4, 32 * H * 4);             // fc: 8 KB
        bulk_g2s(smbase + OFF_FC * 4, fc_w, 32 * H * 4, mbar + 8 * 4);
    }

    // ---- 2) stage small tensors (plain LDG->STS, overlapped with TMA) ----
    const float xv = x[L - 1];
    for (int j = tid; j < ROWS; j += NT) {
        int grow = (j < 64) ? j : j + 64;
        sm[OFF_W0 + j] = Wih0[grow];
        sm[OFF_B0 + j] = bih0[grow] + bhh0[grow];
    }
    for (int j = tid; j < 4 * ROWS; j += NT) {
        int l = j / ROWS, r = j - l * ROWS;
        int grow = (r < 64) ? r : r + 64;
        sm[OFF_BS + j] = bih[l * 256 + grow] + bhh[l * 256 + grow];
    }
    for (int j = tid; j < 512; j += NT) sm[OFF_C1W + j] = c1_w[j];
    if (tid < 32) {
        sm[OFF_FCB + tid] = fc_b[tid];
        sm[OFF_MW + tid]  = mean_w[tid];
        sm[OFF_LSW + tid] = ls_w[tid];
    }
    if (tid < 16) {
        sm[OFF_C1B + tid] = c1_b[tid];
        sm[OFF_C2W + tid] = c2_w[tid];
    }
    if (tid == 1) {
        sm[OFF_SC + 0] = mean_b[0];
        sm[OFF_SC + 1] = ls_b[0];
        sm[OFF_SC + 2] = c2_b[0];
    }
    __syncthreads();   // small tensors + mbarrier init visible to all

    // ---- 3) layer 0: gates from scalar ----
    if (tid < ROWS) sm[OFF_G + tid] = xv * sm[OFF_W0 + tid] + sm[OFF_B0 + tid];
    __syncthreads();
    if (tid < H) {
        float iv = sigf(sm[OFF_G + tid]);
        float gv = tanhf(sm[OFF_G + 64 + tid]);
        float ov = sigf(sm[OFF_G + 128 + tid]);
        sm[OFF_H + tid] = ov * tanhf(iv * gv);
    }

    // ---- 4) layers 1..4 from SMEM; wait on per-layer mbarrier ----
    #pragma unroll
    for (int l = 0; l < 4; ++l) {
        mbar_wait0(mbar + 8 * l);
        __syncthreads();       // TMA data + prev H visible to all
        if (tid < ROWS) {
            const float4* Wr = (const float4*)(sm + OFF_W + (l * ROWS + tid) * H);
            const float4* hv = (const float4*)(sm + OFF_H);
            float acc = sm[OFF_BS + l * ROWS + tid];
            #pragma unroll
            for (int k4 = 0; k4 < 16; ++k4) {
                int kk = (k4 + tid) & 15;       // 16B-granule rotation, conflict-free
                float4 w = Wr[kk];
                float4 h4 = hv[kk];
                acc += w.x * h4.x + w.y * h4.y + w.z * h4.z + w.w * h4.w;
            }
            sm[OFF_G + tid] = acc;
        }
        __syncthreads();
        if (tid < H) {
            float iv = sigf(sm[OFF_G + tid]);
            float gv = tanhf(sm[OFF_G + 64 + tid]);
            float ov = sigf(sm[OFF_G + 128 + tid]);
            sm[OFF_H + tid] = ov * tanhf(iv * gv);
        }
    }

    mbar_wait0(mbar + 8 * 4);  // fc weights
    __syncthreads();

    // ---- 5) head ----
    if (tid < 32) {
        const float4* Wr = (const float4*)(sm + OFF_FC + tid * H);
        const float4* hv = (const float4*)(sm + OFF_H);
        float acc = sm[OFF_FCB + tid];
        #pragma unroll
        for (int k4 = 0; k4 < 16; ++k4) {
            int kk = (k4 + tid) & 15;
            float4 w = Wr[kk];
            float4 h4 = hv[kk];
            acc += w.x * h4.x + w.y * h4.y + w.z * h4.z + w.w * h4.w;
        }
        sm[OFF_Z + tid] = fmaxf(acc, 0.0f);
    }
    __syncthreads();

    if (tid < 16) {
        const float* Wr = sm + OFF_C1W + tid * 32;
        float acc = sm[OFF_C1B + tid];
        #pragma unroll
        for (int k = 0; k < 32; ++k) {
            int kk = (k + 2 * tid) & 31;
            acc += sm[OFF_Z + kk] * Wr[kk];
        }
        sm[OFF_VH + tid] = fmaxf(acc, 0.0f);
    } else if (tid == 16) {
        float acc = sm[OFF_SC + 0];
        #pragma unroll
        for (int k = 0; k < 32; ++k) acc += sm[OFF_Z + k] * sm[OFF_MW + k];
        sm[OFF_SCAL + 0] = acc;
    } else if (tid == 17) {
        float acc = sm[OFF_SC + 1];
        #pragma unroll
        for (int k = 0; k < 32; ++k) acc += sm[OFF_Z + k] * sm[OFF_LSW + k];
        sm[OFF_SCAL + 1] = acc;
    }
    __syncthreads();

    if (tid == 0) {
        float acc = sm[OFF_SC + 2];
        #pragma unroll
        for (int k = 0; k < 16; ++k) acc += sm[OFF_VH + k] * sm[OFF_C2W + k];
        out[0] = sm[OFF_SCAL + 0];
        out[1] = sm[OFF_SCAL + 1];
        out[2] = acc;
    }
}

extern "C" void kernel_launch(void* const* d_in, const int* in_sizes, int n_in,
                              void* d_out, int out_size) {
    const float* x      = (const float*)d_in[0];
    const float* Wih0   = (const float*)d_in[1];
    const float* bih0   = (const float*)d_in[3];
    const float* bhh0   = (const float*)d_in[4];
    const float* Wih    = (const float*)d_in[5];
    const float* bih    = (const float*)d_in[7];
    const float* bhh    = (const float*)d_in[8];
    const float* fc_w   = (const float*)d_in[9];
    const float* fc_b   = (const float*)d_in[10];
    const float* mean_w = (const float*)d_in[11];
    const float* mean_b = (const float*)d_in[12];
    const float* ls_w   = (const float*)d_in[13];
    const float* ls_b   = (const float*)d_in[14];
    const float* c1_w   = (const float*)d_in[15];
    const float* c1_b   = (const float*)d_in[16];
    const float* c2_w   = (const float*)d_in[17];
    const float* c2_b   = (const float*)d_in[18];

    long long L = in_sizes[0];

    cudaFuncSetAttribute(net_kernel,
                         cudaFuncAttributeMaxDynamicSharedMemorySize, SMEM_BYTES);

    net_kernel<<<1, NT, SMEM_BYTES>>>(x, L, Wih0, bih0, bhh0, Wih, bih, bhh,
                                      fc_w, fc_b, mean_w, mean_b, ls_w, ls_b,
                                      c1_w, c1_b, c2_w, c2_b, (float*)d_out);
}